// round 3
// baseline (speedup 1.0000x reference)
#include <cuda_runtime.h>

// Problem constants
#define NTOK  32768          // B*H*W tokens
#define KDIM  256            // embedding dim (C)
#define NE    1024           // codebook size
#define HW    1024           // H*W per batch image
#define NBATCH 32

// Output layout (flattened tuple, float32)
// NOTE: OFF_D*4 % 16 == 4 -> d_out region is only 4-byte aligned; scalar stores only.
#define OFF_ZQ   0
#define OFF_LOSS 8388608
#define OFF_IDX  8388609
#define OFF_D    8421377ll

// GEMM tiling
#define BM 128
#define BN 128
#define BK 16

// Scratch (no allocations allowed)
__device__ float  g_znorm[NTOK];
__device__ float  g_enorm[NE];
__device__ float  g_pval[8][NTOK];
__device__ int    g_pidx[8][NTOK];
__device__ double g_lpart[1024];

// ---------------------------------------------------------------------------
// znorm[t] = sum_c z[b,c,hw]^2  (t = b*1024 + hw). Coalesced: fixed c, tokens
// contiguous.
__global__ __launch_bounds__(256) void znorm_kernel(const float* __restrict__ z) {
    int t  = blockIdx.x * 256 + threadIdx.x;
    int b  = t >> 10;
    int hw = t & 1023;
    const float* base = z + (size_t)b * KDIM * HW + hw;
    float s = 0.f;
#pragma unroll 8
    for (int c = 0; c < KDIM; c++) {
        float v = base[(size_t)c * HW];
        s = fmaf(v, v, s);
    }
    g_znorm[t] = s;
}

// enorm[j] = sum_c e[j,c]^2. One warp per row.
__global__ __launch_bounds__(256) void enorm_kernel(const float* __restrict__ e) {
    int lane = threadIdx.x & 31;
    int wid  = threadIdx.x >> 5;
    int j    = blockIdx.x * 8 + wid;
    const float* row = e + (size_t)j * KDIM;
    float s = 0.f;
#pragma unroll
    for (int u = 0; u < 8; u++) {
        float v = row[lane + 32 * u];
        s = fmaf(v, v, s);
    }
#pragma unroll
    for (int o = 16; o; o >>= 1) s += __shfl_xor_sync(0xFFFFFFFFu, s, o);
    if (lane == 0) g_enorm[j] = s;
}

// ---------------------------------------------------------------------------
// Fused fp32 GEMM: d = znorm + enorm - 2 * (zf @ e^T), writes d_out tile and
// per-(token, j-tile) partial argmin.
__global__ __launch_bounds__(256) void gemm_kernel(const float* __restrict__ z,
                                                   const float* __restrict__ e,
                                                   float* __restrict__ out) {
    __shared__ float As[BK][BM];        // [c][token]
    __shared__ float Bs[BK][BN + 4];    // [c][code]
    __shared__ float s_rval[BM][17];
    __shared__ int   s_ridx[BM][17];

    int tid = threadIdx.x;
    int tx  = tid & 15;
    int ty  = tid >> 4;
    int j0  = blockIdx.x * BN;
    int m0  = blockIdx.y * BM;
    int b   = m0 >> 10;
    int hw0 = m0 & 1023;
    const float* zb = z + (size_t)b * KDIM * HW + hw0;

    float acc[8][8];
#pragma unroll
    for (int i = 0; i < 8; i++)
#pragma unroll
        for (int j = 0; j < 8; j++) acc[i][j] = 0.f;

    for (int ks = 0; ks < KDIM; ks += BK) {
        // A tile: 16 c-rows x 128 tokens = 512 float4, 2 per thread (coalesced)
#pragma unroll
        for (int it = 0; it < 2; it++) {
            int idx  = tid + 256 * it;
            int row  = idx >> 5;
            int col4 = idx & 31;
            float4 v = *(const float4*)(zb + (size_t)(ks + row) * HW + col4 * 4);
            *(float4*)&As[row][col4 * 4] = v;
        }
        // B tile: 128 code rows x 16 c, transpose into [c][code]
#pragma unroll
        for (int it = 0; it < 2; it++) {
            int idx = tid + 256 * it;
            int j   = idx >> 2;
            int q   = idx & 3;
            float4 v = *(const float4*)(e + (size_t)(j0 + j) * KDIM + ks + q * 4);
            Bs[q * 4 + 0][j] = v.x;
            Bs[q * 4 + 1][j] = v.y;
            Bs[q * 4 + 2][j] = v.z;
            Bs[q * 4 + 3][j] = v.w;
        }
        __syncthreads();
#pragma unroll
        for (int k = 0; k < BK; k++) {
            float a[8], bb[8];
            *(float4*)&a[0]  = *(const float4*)&As[k][ty * 4];
            *(float4*)&a[4]  = *(const float4*)&As[k][64 + ty * 4];
            *(float4*)&bb[0] = *(const float4*)&Bs[k][tx * 4];
            *(float4*)&bb[4] = *(const float4*)&Bs[k][64 + tx * 4];
#pragma unroll
            for (int i = 0; i < 8; i++)
#pragma unroll
                for (int j = 0; j < 8; j++)
                    acc[i][j] = fmaf(a[i], bb[j], acc[i][j]);
        }
        __syncthreads();
    }

    // Epilogue: d values, d_out stores (SCALAR: d region is 4B-aligned only),
    // partial argmin.
    float en[8];
#pragma unroll
    for (int j = 0; j < 8; j++) {
        int c = (j < 4) ? (tx * 4 + j) : (64 + tx * 4 + (j - 4));
        en[j] = g_enorm[j0 + c];
    }

#pragma unroll
    for (int i = 0; i < 8; i++) {
        int r  = (i < 4) ? (ty * 4 + i) : (64 + ty * 4 + (i - 4));
        float zn = g_znorm[m0 + r];
        float vals[8];
#pragma unroll
        for (int j = 0; j < 8; j++)
            vals[j] = fmaf(-2.f, acc[i][j], zn + en[j]);

        float* dr = out + OFF_D + (size_t)(m0 + r) * NE + j0;
#pragma unroll
        for (int j = 0; j < 4; j++) dr[tx * 4 + j]      = vals[j];
#pragma unroll
        for (int j = 0; j < 4; j++) dr[64 + tx * 4 + j] = vals[4 + j];

        float bv = vals[0];
        int   bi = j0 + tx * 4;
#pragma unroll
        for (int j = 1; j < 8; j++) {
            int c = (j < 4) ? (tx * 4 + j) : (64 + tx * 4 + (j - 4));
            int gi = j0 + c;
            float v = vals[j];
            if (v < bv || (v == bv && gi < bi)) { bv = v; bi = gi; }
        }
        s_rval[r][tx] = bv;
        s_ridx[r][tx] = bi;
    }
    __syncthreads();

    if (tid < 128) {
        float bv = s_rval[tid][0];
        int   bi = s_ridx[tid][0];
#pragma unroll
        for (int u = 1; u < 16; u++) {
            float v = s_rval[tid][u];
            int  ix = s_ridx[tid][u];
            if (v < bv || (v == bv && ix < bi)) { bv = v; bi = ix; }
        }
        g_pval[blockIdx.x][m0 + tid] = bv;
        g_pidx[blockIdx.x][m0 + tid] = bi;
    }
}

// ---------------------------------------------------------------------------
// Finalize: argmin across 8 j-tiles, write min_idx (as float), gather e rows
// (transposed through smem) to write z_q = z + (e - z) with coalesced NCHW
// stores, accumulate deterministic per-CTA loss partial.
__global__ __launch_bounds__(256) void finalize_kernel(const float* __restrict__ z,
                                                       const float* __restrict__ e,
                                                       float* __restrict__ out) {
    __shared__ int    s_idx[32];
    __shared__ float  s_e[KDIM][33];   // [c][token]
    __shared__ double s_red[8];

    int tid  = threadIdx.x;
    int lane = tid & 31;
    int wid  = tid >> 5;
    int t0   = blockIdx.x * 32;

    if (tid < 32) {
        int t = t0 + tid;
        float bv = g_pval[0][t];
        int   bi = g_pidx[0][t];
#pragma unroll
        for (int u = 1; u < 8; u++) {
            float v = g_pval[u][t];
            int  ix = g_pidx[u][t];
            if (v < bv || (v == bv && ix < bi)) { bv = v; bi = ix; }
        }
        s_idx[tid] = bi;
        out[OFF_IDX + t] = (float)bi;
    }
    __syncthreads();

    // Gather 32 embedding rows, transposed: warp w loads tokens w*4..w*4+3
#pragma unroll
    for (int u = 0; u < 4; u++) {
        int tt = wid * 4 + u;
        const float* row = e + (size_t)s_idx[tt] * KDIM;
#pragma unroll
        for (int v = 0; v < 8; v++) {
            int c = lane + 32 * v;
            s_e[c][tt] = row[c];
        }
    }
    __syncthreads();

    int b   = t0 >> 10;
    int hw0 = t0 & 1023;
    const float* zb = z + (size_t)b * KDIM * HW + hw0;
    float*       qb = out + OFF_ZQ + (size_t)b * KDIM * HW + hw0;

    float ls = 0.f;
#pragma unroll 4
    for (int ci = 0; ci < 32; ci++) {
        int c = wid + ci * 8;
        float zv  = zb[(size_t)c * HW + lane];
        float ev  = s_e[c][lane];
        float dqz = ev - zv;              // matches reference (z_q - z) rounding
        qb[(size_t)c * HW + lane] = zv + dqz;  // straight-through: z + (z_q - z)
        ls = fmaf(dqz, dqz, ls);
    }
#pragma unroll
    for (int o = 16; o; o >>= 1) ls += __shfl_xor_sync(0xFFFFFFFFu, ls, o);
    if (lane == 0) s_red[wid] = (double)ls;
    __syncthreads();
    if (tid == 0) {
        double s = 0.0;
#pragma unroll
        for (int u = 0; u < 8; u++) s += s_red[u];
        g_lpart[blockIdx.x] = s;
    }
}

// Deterministic final loss reduction: loss = (1+beta) * sum / (B*H*W*C)
__global__ __launch_bounds__(256) void loss_kernel(float* __restrict__ out) {
    __shared__ double s_red[256];
    int tid = threadIdx.x;
    double s = 0.0;
#pragma unroll
    for (int u = 0; u < 4; u++) s += g_lpart[tid * 4 + u];
    s_red[tid] = s;
    __syncthreads();
    for (int o = 128; o; o >>= 1) {
        if (tid < o) s_red[tid] += s_red[tid + o];
        __syncthreads();
    }
    if (tid == 0) out[OFF_LOSS] = (float)(1.25 * s_red[0] / 8388608.0);
}

// ---------------------------------------------------------------------------
extern "C" void kernel_launch(void* const* d_in, const int* in_sizes, int n_in,
                              void* d_out, int out_size) {
    const float* z = (const float*)d_in[0];
    const float* e = (const float*)d_in[1];
    float* out = (float*)d_out;

    znorm_kernel<<<NTOK / 256, 256>>>(z);
    enorm_kernel<<<NE / 8, 256>>>(e);
    dim3 grid(NE / BN, NTOK / BM);
    gemm_kernel<<<grid, 256>>>(z, e, out);
    finalize_kernel<<<NTOK / 32, 256>>>(z, e, out);
    loss_kernel<<<1, 256>>>(out);
}

// round 9
// speedup vs baseline: 2.0217x; 2.0217x over previous
#include <cuda_runtime.h>
#include <cuda_bf16.h>
#include <cstdint>

// Problem constants
#define NTOK  32768
#define KDIM  256
#define NE    1024
#define HW    1024

// Output layout (flattened tuple, float32). OFF_D*4 % 16 == 4 -> scalar stores only in d region.
#define OFF_ZQ   0
#define OFF_LOSS 8388608
#define OFF_IDX  8388609
#define OFF_D    8421377ll

#define REFINE_TH 2e-3f

// ---------------------------------------------------------------------------
// Scratch (static device arrays; no allocations allowed)
__device__ float  g_znorm[NTOK];
__device__ float  g_enorm[NE];
__device__ float  g_pval[8][NTOK];   // per n-tile best value
__device__ float  g_psec[8][NTOK];   // per n-tile second-best value
__device__ int    g_pidx[8][NTOK];   // per n-tile best index
__device__ double g_lpart[1024];
__device__ __align__(1024) __nv_bfloat16 g_Ahi[NTOK * KDIM];  // tokens, K-major, bf16
__device__ __align__(1024) __nv_bfloat16 g_Bhi[NE * KDIM];    // codes,  K-major, bf16
__device__ __align__(1024) float g_Ztr[NTOK * KDIM];          // tokens, K-major, fp32 (refine)

// ---------------------------------------------------------------------------
__device__ __forceinline__ uint32_t smem_u32(const void* p) {
    uint32_t a;
    asm("{ .reg .u64 t; cvta.to.shared.u64 t, %1; cvt.u32.u64 %0, t; }" : "=r"(a) : "l"(p));
    return a;
}
__device__ __forceinline__ void cp16(uint32_t dst, const void* src) {
    asm volatile("cp.async.cg.shared.global [%0], [%1], 16;" :: "r"(dst), "l"(src));
}
__device__ __forceinline__ void cp_commit() {
    asm volatile("cp.async.commit_group;" ::: "memory");
}
template <int N> __device__ __forceinline__ void cp_wait() {
    asm volatile("cp.async.wait_group %0;" :: "n"(N) : "memory");
}
__device__ __forceinline__ void ldsm4(uint32_t& r0, uint32_t& r1, uint32_t& r2, uint32_t& r3,
                                      uint32_t addr) {
    asm volatile("ldmatrix.sync.aligned.m8n8.x4.shared.b16 {%0,%1,%2,%3}, [%4];"
                 : "=r"(r0), "=r"(r1), "=r"(r2), "=r"(r3) : "r"(addr));
}
__device__ __forceinline__ void mma16816(float* c, const uint32_t* a, const uint32_t* b) {
    asm volatile(
        "mma.sync.aligned.m16n8k16.row.col.f32.bf16.bf16.f32 "
        "{%0,%1,%2,%3}, {%4,%5,%6,%7}, {%8,%9}, {%0,%1,%2,%3};"
        : "+f"(c[0]), "+f"(c[1]), "+f"(c[2]), "+f"(c[3])
        : "r"(a[0]), "r"(a[1]), "r"(a[2]), "r"(a[3]), "r"(b[0]), "r"(b[1]));
}
// Merge (b1,i1,b2) <- other (ob1,oi1,ob2); strict compare + index tie-break.
#define MERGE3(b1, i1, b2, ob1, oi1, ob2) do {                     \
    if ((ob1) < (b1) || ((ob1) == (b1) && (oi1) < (i1))) {         \
        (b2) = fminf((b1), (ob2)); (b1) = (ob1); (i1) = (oi1);     \
    } else {                                                       \
        (b2) = fminf((b2), (ob1));                                 \
    }                                                              \
} while (0)

// ---------------------------------------------------------------------------
// prep_e: e -> bf16 K-major (131072 float2 pairs)
__global__ __launch_bounds__(256) void prep_e(const float* __restrict__ e) {
    int i = blockIdx.x * 256 + threadIdx.x;
    float2 v = ((const float2*)e)[i];
    __nv_bfloat162 hp;
    hp.x = __float2bfloat16(v.x);
    hp.y = __float2bfloat16(v.y);
    ((uint32_t*)g_Bhi)[i] = *(uint32_t*)&hp;
}

__global__ __launch_bounds__(256) void enorm_kernel(const float* __restrict__ e) {
    int lane = threadIdx.x & 31;
    int wid  = threadIdx.x >> 5;
    int j    = blockIdx.x * 8 + wid;
    const float* row = e + (size_t)j * KDIM;
    float s = 0.f;
#pragma unroll
    for (int u = 0; u < 8; u++) {
        float v = row[lane + 32 * u];
        s = fmaf(v, v, s);
    }
#pragma unroll
    for (int o = 16; o; o >>= 1) s += __shfl_xor_sync(0xFFFFFFFFu, s, o);
    if (lane == 0) g_enorm[j] = s;
}

// prep_z: NCHW -> token-major: bf16 (g_Ahi), fp32 (g_Ztr), znorm. 32 tokens/block.
__global__ __launch_bounds__(256) void prep_z(const float* __restrict__ z) {
    __shared__ float ts[KDIM][33];
    __shared__ float zp[8][32];
    int tid = threadIdx.x;
    int tb  = blockIdx.x;
    int b   = tb >> 5;
    int hw0 = (tb * 32) & 1023;
    const float* zb = z + (size_t)b * KDIM * HW + hw0;
    int lane32 = tid & 31, cb = tid >> 5;
#pragma unroll
    for (int i = 0; i < 32; i++) {
        int c = i * 8 + cb;
        ts[c][lane32] = zb[(size_t)c * HW + lane32];
    }
    __syncthreads();
    // znorm partials
    float s = 0.f;
#pragma unroll
    for (int i = 0; i < 32; i++) {
        float v = ts[cb * 32 + i][lane32];
        s = fmaf(v, v, s);
    }
    zp[cb][lane32] = s;
    __syncthreads();
    if (tid < 32) {
        float t = 0.f;
#pragma unroll
        for (int u = 0; u < 8; u++) t += zp[u][tid];
        g_znorm[tb * 32 + tid] = t;
    }
    // write fp32 + bf16 token rows
    int t = tid >> 3, part = tid & 7;
    float*    ztr = g_Ztr + (size_t)(tb * 32 + t) * KDIM + part * 32;
    uint32_t* ah  = (uint32_t*)g_Ahi + (size_t)(tb * 32 + t) * 128 + part * 16;
#pragma unroll
    for (int i = 0; i < 32; i++) ztr[i] = ts[part * 32 + i][t];
#pragma unroll
    for (int i = 0; i < 16; i++) {
        __nv_bfloat162 hp;
        hp.x = __float2bfloat16(ts[part * 32 + 2 * i][t]);
        hp.y = __float2bfloat16(ts[part * 32 + 2 * i + 1][t]);
        ah[i] = *(uint32_t*)&hp;
    }
}

// ---------------------------------------------------------------------------
// GEMM: 128x128 tile, K=256, bf16 HMMA, 2-stage cp.async, fused d epilogue +
// per-token (best, idx, second) partials.
#define SM_STAGE 32768
#define SM_EN    65536
#define SM_RED   66048       // 128 rows * 4 warps * (v1, v2, idx)
#define SM_GTOT  72192

__global__ __launch_bounds__(256, 2) void gemm_mma(float* __restrict__ out) {
    extern __shared__ char smem[];
    uint32_t sb = smem_u32(smem);
    int tid  = threadIdx.x;
    int lane = tid & 31, warp = tid >> 5;
    int wy = warp & 1, wx = warp >> 1;          // 2 (M) x 4 (N) warps
    int j0 = blockIdx.x * 128;
    int m0 = blockIdx.y * 128;

    float* s_en = (float*)(smem + SM_EN);
    if (tid < 128) s_en[tid] = g_enorm[j0 + tid];

    float acc[4][4][4];
#pragma unroll
    for (int a = 0; a < 4; a++)
#pragma unroll
        for (int b = 0; b < 4; b++)
#pragma unroll
            for (int c = 0; c < 4; c++) acc[a][b][c] = 0.f;

    // chunk loader: chunk c (64 k) into stage s
    auto load_chunk = [&](int c, int s) {
        uint32_t base_a = sb + s * SM_STAGE;
        uint32_t base_b = base_a + 16384;
#pragma unroll
        for (int i = 0; i < 4; i++) {
            int ch = tid + i * 256;               // 0..1023
            int r = ch >> 3, cc = ch & 7;
            uint32_t sw = (uint32_t)(r * 128 + ((cc ^ (r & 7)) << 4));
            cp16(base_a + sw, (const char*)g_Ahi + ((size_t)(m0 + r) * KDIM + c * 64 + cc * 8) * 2);
            cp16(base_b + sw, (const char*)g_Bhi + ((size_t)(j0 + r) * KDIM + c * 64 + cc * 8) * 2);
        }
        cp_commit();
    };

    load_chunk(0, 0);
    load_chunk(1, 1);

#pragma unroll
    for (int c = 0; c < 4; c++) {
        if (c == 3) cp_wait<0>(); else cp_wait<1>();
        __syncthreads();
        uint32_t sa  = sb + (c & 1) * SM_STAGE;
        uint32_t sbb = sa + 16384;
#pragma unroll
        for (int k16 = 0; k16 < 4; k16++) {
            uint32_t af[4][4];
#pragma unroll
            for (int mf = 0; mf < 4; mf++) {
                int row = wy * 64 + mf * 16 + (lane & 15);
                int ch  = k16 * 2 + (lane >> 4);
                uint32_t addr = sa + row * 128 + (((ch ^ (row & 7))) << 4);
                ldsm4(af[mf][0], af[mf][1], af[mf][2], af[mf][3], addr);
            }
            uint32_t bf[4][2];
#pragma unroll
            for (int h = 0; h < 2; h++) {
                int row = wx * 32 + h * 16 + ((lane >> 4) << 3) + (lane & 7);
                int ch  = k16 * 2 + ((lane >> 3) & 1);
                uint32_t addr = sbb + row * 128 + (((ch ^ (row & 7))) << 4);
                uint32_t r0, r1, r2, r3;
                ldsm4(r0, r1, r2, r3, addr);
                bf[2 * h][0] = r0; bf[2 * h][1] = r1;
                bf[2 * h + 1][0] = r2; bf[2 * h + 1][1] = r3;
            }
#pragma unroll
            for (int mf = 0; mf < 4; mf++)
#pragma unroll
                for (int nf = 0; nf < 4; nf++)
                    mma16816(acc[mf][nf], af[mf], bf[nf]);
        }
        __syncthreads();
        if (c + 2 < 4) load_chunk(c + 2, c & 1);
    }

    // ---- Epilogue: d = zn + en - 2*acc; scalar stores (4B-aligned region);
    // per-row (b1, i1, b2) partials. Warp wx owns cols [wx*32, wx*32+32).
    float* sv1 = (float*)(smem + SM_RED);
    float* sv2 = sv1 + 512;
    int*   six = (int*)(sv2 + 512);

#pragma unroll
    for (int mf = 0; mf < 4; mf++) {
#pragma unroll
        for (int h = 0; h < 2; h++) {
            int row = wy * 64 + mf * 16 + (lane >> 2) + 8 * h;
            float zn = g_znorm[m0 + row];
            float b1 = 3.4e38f, b2 = 3.4e38f;
            int   i1 = 0;
            float* drow = out + OFF_D + (size_t)(m0 + row) * NE + j0;
#pragma unroll
            for (int nf = 0; nf < 4; nf++) {
#pragma unroll
                for (int q = 0; q < 2; q++) {
                    int col = wx * 32 + nf * 8 + 2 * (lane & 3) + q;
                    float v = fmaf(-2.f, acc[mf][nf][2 * h + q], zn + s_en[col]);
                    drow[col] = v;
                    if (v < b1)      { b2 = b1; b1 = v; i1 = j0 + col; }
                    else if (v < b2) { b2 = v; }
                }
            }
            // merge across the 4 lanes sharing this row
#pragma unroll
            for (int off = 1; off < 4; off <<= 1) {
                float ob1 = __shfl_xor_sync(0xFFFFFFFFu, b1, off);
                float ob2 = __shfl_xor_sync(0xFFFFFFFFu, b2, off);
                int   oi1 = __shfl_xor_sync(0xFFFFFFFFu, i1, off);
                MERGE3(b1, i1, b2, ob1, oi1, ob2);
            }
            if ((lane & 3) == 0) {
                int rloc = row;                    // 0..127
                sv1[rloc * 4 + wx] = b1;
                sv2[rloc * 4 + wx] = b2;
                six[rloc * 4 + wx] = i1;
            }
        }
    }
    __syncthreads();
    if (tid < 128) {
        float b1 = sv1[tid * 4], b2 = sv2[tid * 4];
        int   i1 = six[tid * 4];
#pragma unroll
        for (int u = 1; u < 4; u++) {
            float ob1 = sv1[tid * 4 + u], ob2 = sv2[tid * 4 + u];
            int   oi1 = six[tid * 4 + u];
            MERGE3(b1, i1, b2, ob1, oi1, ob2);
        }
        g_pval[blockIdx.x][m0 + tid] = b1;
        g_psec[blockIdx.x][m0 + tid] = b2;
        g_pidx[blockIdx.x][m0 + tid] = i1;
    }
}

// ---------------------------------------------------------------------------
// Finalize: merge tiles, exact-refine ambiguous tokens, write min_idx,
// gather z_q, loss partials.
__global__ __launch_bounds__(256) void finalize_kernel(const float* __restrict__ z,
                                                       const float* __restrict__ e,
                                                       float* __restrict__ out) {
    __shared__ int    s_idx[32];
    __shared__ float  s_b1[32], s_b2[32];
    __shared__ float  s_e[KDIM][33];
    __shared__ double s_red[8];

    int tid  = threadIdx.x;
    int lane = tid & 31;
    int wid  = tid >> 5;
    int t0   = blockIdx.x * 32;

    if (tid < 32) {
        int t = t0 + tid;
        float b1 = g_pval[0][t], b2 = g_psec[0][t];
        int   i1 = g_pidx[0][t];
#pragma unroll
        for (int u = 1; u < 8; u++) {
            float ob1 = g_pval[u][t], ob2 = g_psec[u][t];
            int   oi1 = g_pidx[u][t];
            MERGE3(b1, i1, b2, ob1, oi1, ob2);
        }
        s_idx[tid] = i1;
        s_b1[tid] = b1;
        s_b2[tid] = b2;
    }
    __syncthreads();

    // exact refinement for ambiguous tokens (whole warp per token)
#pragma unroll
    for (int k = 0; k < 4; k++) {
        int tl = wid + k * 8;
        if (s_b2[tl] - s_b1[tl] < REFINE_TH) {
            int t = t0 + tl;
            float zr[8];
            const float* zrow = g_Ztr + (size_t)t * KDIM;
#pragma unroll
            for (int u = 0; u < 8; u++) zr[u] = zrow[lane + 32 * u];
            float zn = g_znorm[t];
            float thresh = s_b1[tl] + REFINE_TH;
            const float* drow = out + OFF_D + (size_t)t * NE;
            float bestv = 3.4e38f;
            int   besti = s_idx[tl];
            for (int i = 0; i < 32; i++) {
                float dv = drow[lane + 32 * i];
                unsigned msk = __ballot_sync(0xFFFFFFFFu, dv < thresh);
                while (msk) {
                    int src = __ffs(msk) - 1;
                    msk &= msk - 1;
                    int j = src + 32 * i;
                    const float* erow = e + (size_t)j * KDIM;
                    float d = 0.f;
#pragma unroll
                    for (int u = 0; u < 8; u++) d = fmaf(zr[u], erow[lane + 32 * u], d);
#pragma unroll
                    for (int o = 16; o; o >>= 1) d += __shfl_xor_sync(0xFFFFFFFFu, d, o);
                    if (lane == 0) {
                        float ex = fmaf(-2.f, d, zn + g_enorm[j]);
                        if (ex < bestv) { bestv = ex; besti = j; }
                    }
                }
            }
            if (lane == 0) s_idx[tl] = besti;
        }
    }
    __syncthreads();

    if (tid < 32) out[OFF_IDX + t0 + tid] = (float)s_idx[tid];

    // gather embedding rows (transposed), write z_q, loss partials
#pragma unroll
    for (int u = 0; u < 4; u++) {
        int tt = wid * 4 + u;
        const float* row = e + (size_t)s_idx[tt] * KDIM;
#pragma unroll
        for (int v = 0; v < 8; v++) {
            int c = lane + 32 * v;
            s_e[c][tt] = row[c];
        }
    }
    __syncthreads();

    int b   = t0 >> 10;
    int hw0 = t0 & 1023;
    const float* zb = z + (size_t)b * KDIM * HW + hw0;
    float*       qb = out + OFF_ZQ + (size_t)b * KDIM * HW + hw0;

    float ls = 0.f;
#pragma unroll 4
    for (int ci = 0; ci < 32; ci++) {
        int c = wid + ci * 8;
        float zv  = zb[(size_t)c * HW + lane];
        float ev  = s_e[c][lane];
        float dqz = ev - zv;
        qb[(size_t)c * HW + lane] = zv + dqz;
        ls = fmaf(dqz, dqz, ls);
    }
#pragma unroll
    for (int o = 16; o; o >>= 1) ls += __shfl_xor_sync(0xFFFFFFFFu, ls, o);
    if (lane == 0) s_red[wid] = (double)ls;
    __syncthreads();
    if (tid == 0) {
        double s = 0.0;
#pragma unroll
        for (int u = 0; u < 8; u++) s += s_red[u];
        g_lpart[blockIdx.x] = s;
    }
}

__global__ __launch_bounds__(256) void loss_kernel(float* __restrict__ out) {
    __shared__ double s_red[256];
    int tid = threadIdx.x;
    double s = 0.0;
#pragma unroll
    for (int u = 0; u < 4; u++) s += g_lpart[tid * 4 + u];
    s_red[tid] = s;
    __syncthreads();
    for (int o = 128; o; o >>= 1) {
        if (tid < o) s_red[tid] += s_red[tid + o];
        __syncthreads();
    }
    if (tid == 0) out[OFF_LOSS] = (float)(1.25 * s_red[0] / 8388608.0);
}

// ---------------------------------------------------------------------------
extern "C" void kernel_launch(void* const* d_in, const int* in_sizes, int n_in,
                              void* d_out, int out_size) {
    const float* z = (const float*)d_in[0];
    const float* e = (const float*)d_in[1];
    float* out = (float*)d_out;

    cudaFuncSetAttribute(gemm_mma, cudaFuncAttributeMaxDynamicSharedMemorySize, SM_GTOT);

    prep_e<<<512, 256>>>(e);
    enorm_kernel<<<NE / 8, 256>>>(e);
    prep_z<<<1024, 256>>>(z);
    {
        dim3 grid(8, 256);          // x = n-tiles (fast), y = m-tiles
        gemm_mma<<<grid, 256, SM_GTOT>>>(out);
    }
    finalize_kernel<<<NTOK / 32, 256>>>(z, e, out);
    loss_kernel<<<1, 256>>>(out);
}